// round 1
// baseline (speedup 1.0000x reference)
#include <cuda_runtime.h>

// GarNet aggregation: out[b, s*64+n] = (sum_v w) * (sum_v w*fi) / (128*128)
// with w = exp(-d_av^2).  B=4096, V=128, S=16, N=64.
static constexpr int Bc = 4096;
static constexpr int Vc = 128;
static constexpr int Sc = 16;
static constexpr int Nc = 64;
static constexpr int BPC = 4;                  // batches per CTA
static constexpr int WSTRIDE = Vc * Sc + 16;   // padded smem stride in floats (bank stagger)

typedef unsigned long long u64;

__device__ __forceinline__ u64 bcast2(float x) {
    u64 r; unsigned xi = __float_as_uint(x);
    asm("mov.b64 %0, {%1, %1};" : "=l"(r) : "r"(xi));
    return r;
}
__device__ __forceinline__ void ffma2(u64 &c, u64 a, u64 b) {
    asm("fma.rn.f32x2 %0, %1, %2, %0;" : "+l"(c) : "l"(a), "l"(b));
}
__device__ __forceinline__ float lo32(u64 v) { return __uint_as_float((unsigned)(v & 0xffffffffull)); }
__device__ __forceinline__ float hi32(u64 v) { return __uint_as_float((unsigned)(v >> 32)); }

__global__ __launch_bounds__(64)
void garnet_kernel(const float* __restrict__ fi,
                   const float* __restrict__ dav,
                   float* __restrict__ out) {
    __shared__ __align__(16) float s_w[BPC * WSTRIDE];
    __shared__ float s_wbar[BPC * Sc];

    const int t  = threadIdx.x;
    const int bl = t >> 4;   // 0..3 : batch within CTA
    const int l  = t & 15;   // 0..15: lane within batch group
    const long b = (long)blockIdx.x * BPC + bl;

    // ---------------- Phase 1: w = exp(-d^2) into smem, plus column sums ----
    {
        const float4* __restrict__ dsrc = (const float4*)(dav + b * (long)(Vc * Sc));
        float* wdst = s_w + bl * WSTRIDE;
        // float4 index pattern j*16+l: s of element k is ((l&3)*4 + k)
        float wb0 = 0.f, wb1 = 0.f, wb2 = 0.f, wb3 = 0.f;
        #pragma unroll 8
        for (int j = 0; j < 32; j++) {
            int idx = j * 16 + l;             // 0..511 float4s  (coalesced)
            float4 d4 = dsrc[idx];
            float4 w4;
            w4.x = __expf(-d4.x * d4.x);
            w4.y = __expf(-d4.y * d4.y);
            w4.z = __expf(-d4.z * d4.z);
            w4.w = __expf(-d4.w * d4.w);
            *(float4*)(wdst + idx * 4) = w4;  // conflict-free (lanes contiguous)
            wb0 += w4.x; wb1 += w4.y; wb2 += w4.z; wb3 += w4.w;
        }
        // Reduce across lanes {c, c+4, c+8, c+12} within each 16-lane group.
        wb0 += __shfl_xor_sync(0xffffffffu, wb0, 8, 16);
        wb0 += __shfl_xor_sync(0xffffffffu, wb0, 4, 16);
        wb1 += __shfl_xor_sync(0xffffffffu, wb1, 8, 16);
        wb1 += __shfl_xor_sync(0xffffffffu, wb1, 4, 16);
        wb2 += __shfl_xor_sync(0xffffffffu, wb2, 8, 16);
        wb2 += __shfl_xor_sync(0xffffffffu, wb2, 4, 16);
        wb3 += __shfl_xor_sync(0xffffffffu, wb3, 8, 16);
        wb3 += __shfl_xor_sync(0xffffffffu, wb3, 4, 16);
        if (l < 4) {
            float* wbar = s_wbar + bl * Sc + l * 4;
            wbar[0] = wb0; wbar[1] = wb1; wbar[2] = wb2; wbar[3] = wb3;
        }
    }
    __syncthreads();

    // ---------------- Phase 2: hi accumulation, fi read once from HBM -------
    u64 acc[32];                 // acc[sp*4+j]: lo = s=2sp, hi = s=2sp+1, n = l*4+j
    #pragma unroll
    for (int i = 0; i < 32; i++) acc[i] = 0ull;

    const float4* __restrict__ fsrc = (const float4*)(fi + b * (long)(Vc * Nc)) + l;
    const float* wrow = s_w + bl * WSTRIDE;

    float4 f4 = fsrc[0];
    #pragma unroll 4
    for (int v = 0; v < Vc; v++) {
        float4 fn = f4;
        if (v + 1 < Vc) fn = fsrc[(v + 1) * (Nc / 4)];   // prefetch next v
        const ulonglong2* wp = (const ulonglong2*)(wrow + v * Sc);
        ulonglong2 wA = wp[0], wB = wp[1], wC = wp[2], wD = wp[3];
        u64 wpair[8] = { wA.x, wA.y, wB.x, wB.y, wC.x, wC.y, wD.x, wD.y };
        u64 fb[4] = { bcast2(f4.x), bcast2(f4.y), bcast2(f4.z), bcast2(f4.w) };
        #pragma unroll
        for (int sp = 0; sp < 8; sp++) {
            #pragma unroll
            for (int j = 0; j < 4; j++)
                ffma2(acc[sp * 4 + j], wpair[sp], fb[j]);
        }
        f4 = fn;
    }

    // ---------------- Epilogue: scale and write ------------------------------
    const float inv = 1.0f / 16384.0f;   // 1/(V*V)
    float* obase = out + b * (long)(Sc * Nc) + l * 4;
    #pragma unroll
    for (int sp = 0; sp < 8; sp++) {
        float se = s_wbar[bl * Sc + 2 * sp]     * inv;
        float so = s_wbar[bl * Sc + 2 * sp + 1] * inv;
        float4 oe, oo;
        oe.x = lo32(acc[sp * 4 + 0]) * se;
        oe.y = lo32(acc[sp * 4 + 1]) * se;
        oe.z = lo32(acc[sp * 4 + 2]) * se;
        oe.w = lo32(acc[sp * 4 + 3]) * se;
        oo.x = hi32(acc[sp * 4 + 0]) * so;
        oo.y = hi32(acc[sp * 4 + 1]) * so;
        oo.z = hi32(acc[sp * 4 + 2]) * so;
        oo.w = hi32(acc[sp * 4 + 3]) * so;
        *(float4*)(obase + (2 * sp) * Nc)     = oe;
        *(float4*)(obase + (2 * sp + 1) * Nc) = oo;
    }
}

extern "C" void kernel_launch(void* const* d_in, const int* in_sizes, int n_in,
                              void* d_out, int out_size) {
    const float* fi  = (const float*)d_in[0];
    const float* dav = (const float*)d_in[1];
    // Defensive: identify by element count (fi_v has 4096*128*64 = 33554432 elems)
    if (n_in >= 2 && in_sizes[0] == Bc * Vc * Sc) {
        const float* tmp = fi; fi = dav; dav = tmp;
    }
    garnet_kernel<<<Bc / BPC, 64>>>(fi, dav, (float*)d_out);
}

// round 2
// speedup vs baseline: 1.2372x; 1.2372x over previous
#include <cuda_runtime.h>

// GarNet aggregation: out[b, s*64+n] = (sum_v w[v,s]) * (sum_v w[v,s]*fi[v,n]) / (128*128)
// with w = exp(-d_av^2).  B=4096, V=128, S=16, N=64.
//
// R2 design: one warp per batch (16 n-groups x 2 s-halves), V chunked by 32,
// warp-private smem w tile, no __syncthreads, launch_bounds(256,4) -> 32 warps/SM.
static constexpr int Bc = 4096;
static constexpr int Vc = 128;
static constexpr int Sc = 16;
static constexpr int Nc = 64;
static constexpr int WPB = 8;          // warps (=batches) per CTA
static constexpr int VCHUNK = 32;      // v per chunk
static constexpr int NCHUNK = Vc / VCHUNK;
static constexpr int WSTR = VCHUNK * Sc + 8;   // padded per-warp w stride (floats)

typedef unsigned long long u64;

__device__ __forceinline__ u64 bcast2(float x) {
    u64 r; unsigned xi = __float_as_uint(x);
    asm("mov.b64 %0, {%1, %1};" : "=l"(r) : "r"(xi));
    return r;
}
__device__ __forceinline__ void ffma2(u64 &c, u64 a, u64 b) {
    asm("fma.rn.f32x2 %0, %1, %2, %0;" : "+l"(c) : "l"(a), "l"(b));
}
__device__ __forceinline__ float lo32(u64 v) { return __uint_as_float((unsigned)(v & 0xffffffffull)); }
__device__ __forceinline__ float hi32(u64 v) { return __uint_as_float((unsigned)(v >> 32)); }

__global__ __launch_bounds__(256, 4)
void garnet_kernel(const float* __restrict__ fi,
                   const float* __restrict__ dav,
                   float* __restrict__ out) {
    __shared__ __align__(16) float s_w[WPB * WSTR];
    __shared__ float s_wbar[WPB][Sc];

    const int warp = threadIdx.x >> 5;
    const int lane = threadIdx.x & 31;
    const int ng   = lane & 15;   // n-group: owns n = ng*4 .. ng*4+3
    const int sh   = lane >> 4;   // s-half:  owns s = sh*8 .. sh*8+7
    const long b   = (long)blockIdx.x * WPB + warp;

    const float4* __restrict__ dsrc = (const float4*)(dav + b * (long)(Vc * Sc));
    const float4* __restrict__ fsrc = (const float4*)(fi  + b * (long)(Vc * Nc)) + ng;
    float* __restrict__ wreg = s_w + warp * WSTR;

    u64 acc[16];                       // acc[sp*4+j]: lo = s=sh*8+2sp, hi = s+1, n = ng*4+j
    #pragma unroll
    for (int i = 0; i < 16; i++) acc[i] = 0ull;

    float wb0 = 0.f, wb1 = 0.f, wb2 = 0.f, wb3 = 0.f;   // partial col-sums, s=(lane&3)*4+k

    for (int c = 0; c < NCHUNK; c++) {
        // ---- phase 1: w = exp(-d^2) for this chunk, warp-private smem tile ----
        #pragma unroll
        for (int j = 0; j < 4; j++) {
            int t4 = j * 32 + lane;                 // 0..127 float4s within chunk
            float4 d4 = dsrc[c * (VCHUNK * Sc / 4) + t4];
            float4 w4;
            w4.x = __expf(-d4.x * d4.x);
            w4.y = __expf(-d4.y * d4.y);
            w4.z = __expf(-d4.z * d4.z);
            w4.w = __expf(-d4.w * d4.w);
            *(float4*)(wreg + t4 * 4) = w4;
            wb0 += w4.x; wb1 += w4.y; wb2 += w4.z; wb3 += w4.w;
        }
        __syncwarp();

        // ---- phase 2: accumulate hi over this chunk, fi read once from HBM ----
        #pragma unroll 4
        for (int vv = 0; vv < VCHUNK; vv++) {
            float4 f4 = fsrc[(c * VCHUNK + vv) * (Nc / 4)];
            const ulonglong2* wp = (const ulonglong2*)(wreg + vv * Sc + sh * 8);
            ulonglong2 wA = wp[0], wB = wp[1];
            u64 w0 = wA.x, w1 = wA.y, w2 = wB.x, w3 = wB.y;  // s pairs within half
            u64 fb0 = bcast2(f4.x), fb1 = bcast2(f4.y);
            u64 fb2 = bcast2(f4.z), fb3 = bcast2(f4.w);
            ffma2(acc[ 0], w0, fb0); ffma2(acc[ 1], w0, fb1);
            ffma2(acc[ 2], w0, fb2); ffma2(acc[ 3], w0, fb3);
            ffma2(acc[ 4], w1, fb0); ffma2(acc[ 5], w1, fb1);
            ffma2(acc[ 6], w1, fb2); ffma2(acc[ 7], w1, fb3);
            ffma2(acc[ 8], w2, fb0); ffma2(acc[ 9], w2, fb1);
            ffma2(acc[10], w2, fb2); ffma2(acc[11], w2, fb3);
            ffma2(acc[12], w3, fb0); ffma2(acc[13], w3, fb1);
            ffma2(acc[14], w3, fb2); ffma2(acc[15], w3, fb3);
        }
        __syncwarp();   // w tile is overwritten next chunk
    }

    // ---- wbar: reduce col-sums across the 8 lanes of each (lane&3) class ----
    wb0 += __shfl_xor_sync(0xffffffffu, wb0, 16);
    wb0 += __shfl_xor_sync(0xffffffffu, wb0, 8);
    wb0 += __shfl_xor_sync(0xffffffffu, wb0, 4);
    wb1 += __shfl_xor_sync(0xffffffffu, wb1, 16);
    wb1 += __shfl_xor_sync(0xffffffffu, wb1, 8);
    wb1 += __shfl_xor_sync(0xffffffffu, wb1, 4);
    wb2 += __shfl_xor_sync(0xffffffffu, wb2, 16);
    wb2 += __shfl_xor_sync(0xffffffffu, wb2, 8);
    wb2 += __shfl_xor_sync(0xffffffffu, wb2, 4);
    wb3 += __shfl_xor_sync(0xffffffffu, wb3, 16);
    wb3 += __shfl_xor_sync(0xffffffffu, wb3, 8);
    wb3 += __shfl_xor_sync(0xffffffffu, wb3, 4);
    if (lane < 4) {
        s_wbar[warp][lane * 4 + 0] = wb0;
        s_wbar[warp][lane * 4 + 1] = wb1;
        s_wbar[warp][lane * 4 + 2] = wb2;
        s_wbar[warp][lane * 4 + 3] = wb3;
    }
    __syncwarp();

    // ---- epilogue: out = wbar * acc / (V*V) ----
    const float inv = 1.0f / 16384.0f;
    float* obase = out + b * (long)(Sc * Nc) + ng * 4;
    #pragma unroll
    for (int sp = 0; sp < 4; sp++) {
        int s0 = sh * 8 + 2 * sp;
        float se = s_wbar[warp][s0]     * inv;
        float so = s_wbar[warp][s0 + 1] * inv;
        float4 oe, oo;
        oe.x = lo32(acc[sp * 4 + 0]) * se;
        oe.y = lo32(acc[sp * 4 + 1]) * se;
        oe.z = lo32(acc[sp * 4 + 2]) * se;
        oe.w = lo32(acc[sp * 4 + 3]) * se;
        oo.x = hi32(acc[sp * 4 + 0]) * so;
        oo.y = hi32(acc[sp * 4 + 1]) * so;
        oo.z = hi32(acc[sp * 4 + 2]) * so;
        oo.w = hi32(acc[sp * 4 + 3]) * so;
        *(float4*)(obase + s0 * Nc)       = oe;
        *(float4*)(obase + (s0 + 1) * Nc) = oo;
    }
}

extern "C" void kernel_launch(void* const* d_in, const int* in_sizes, int n_in,
                              void* d_out, int out_size) {
    const float* fi  = (const float*)d_in[0];
    const float* dav = (const float*)d_in[1];
    // Defensive: identify by element count (fi_v has 4096*128*64 elems)
    if (n_in >= 2 && in_sizes[0] == Bc * Vc * Sc) {
        const float* tmp = fi; fi = dav; dav = tmp;
    }
    garnet_kernel<<<Bc / WPB, WPB * 32>>>(fi, dav, (float*)d_out);
}